// round 10
// baseline (speedup 1.0000x reference)
#include <cuda_runtime.h>
#include <float.h>

#define BN 512
#define DN 256
#define NT 16            // 512 / 32 tiles per dim
#define NBLK 136         // NT*(NT+1)/2 upper-triangular tiles
#define MBLK 128         // mine kernel CTAs (4 warps = 4 anchors each)
#define SPAD 68          // smem row stride (float2 units) - conflict padding

// Scratch (no allocations allowed)
__device__ float g_pd[BN * BN];
__device__ float g_ploss[BN];
__device__ int   g_pcnt[BN];
__device__ unsigned int g_done;    // reset by last CTA each call

__device__ __forceinline__ unsigned f2tf(float x) {
    unsigned r;
    asm("cvt.rna.tf32.f32 %0, %1;" : "=r"(r) : "f"(x));
    return r;
}

__device__ __forceinline__ void mma_tf32(float c[4],
                                         unsigned a0, unsigned a1, unsigned a2, unsigned a3,
                                         unsigned b0, unsigned b1) {
    asm volatile(
        "mma.sync.aligned.m16n8k8.row.col.f32.tf32.tf32.f32 "
        "{%0,%1,%2,%3}, {%4,%5,%6,%7}, {%8,%9}, {%0,%1,%2,%3};\n"
        : "+f"(c[0]), "+f"(c[1]), "+f"(c[2]), "+f"(c[3])
        : "r"(a0), "r"(a1), "r"(a2), "r"(a3), "r"(b0), "r"(b1));
}

// ---------------------------------------------------------------------------
// Kernel A: symmetric pairwise sq-distance GEMM on tensor cores (3xTF32).
// 136 CTAs x 256 threads (8 warps). Warp w -> output block (mb=w>>2, nb=w&3):
// rows i0+mb*16..+15, cols j0+nb*8..+7. K processed in 4 chunks of 64; inputs
// split x = hi + lo (tf32), dot = hi*hi + hi*lo + lo*hi. hi/lo interleaved as
// float2 in smem so each fragment pair is one LDS.64. Norms fused in staging.
// ---------------------------------------------------------------------------
__global__ void __launch_bounds__(256) pd_mma(const float* __restrict__ emb) {
    __shared__ __align__(16) uint2 Apk[32][SPAD];   // [row][k] = {hi, lo}
    __shared__ __align__(16) uint2 Bpk[32][SPAD];
    __shared__ float sqA[32], sqB[32];

    const int tid = threadIdx.x;
    const int lane = tid & 31;
    const int w = tid >> 5;

    // decode linear block -> (ti, tj), ti <= tj
    int b = blockIdx.x, ti = 0;
    while (b >= NT - ti) { b -= NT - ti; ti++; }
    const int tj = ti + b;
    const int i0 = ti * 32, j0 = tj * 32;

    // staging role: thread -> (row, 8-col span)
    const int srow = tid >> 3;          // 0..31
    const int soff = (tid & 7) * 8;     // 0..56
    const float* Abase = emb + (i0 + srow) * DN + soff;
    const float* Bbase = emb + (j0 + srow) * DN + soff;

    // MMA role
    const int mb = w >> 2;              // 0..1
    const int nb = w & 3;               // 0..3
    const int g  = lane >> 2;           // groupID 0..7
    const int t4 = lane & 3;            // threadID_in_group
    const int ar0 = mb * 16 + g;        // A frag rows
    const int ar1 = ar0 + 8;
    const int brn = nb * 8 + g;         // B frag n-row

    float acc[4] = {0.f, 0.f, 0.f, 0.f};
    float na = 0.f, nbm = 0.f;

    #pragma unroll 1
    for (int c = 0; c < 4; c++) {
        const int k0 = c * 64;
        __syncthreads();
        // ---- stage + convert chunk [k0, k0+64) ----
        {
            float4 x0 = *(const float4*)(Abase + k0);
            float4 x1 = *(const float4*)(Abase + k0 + 4);
            float4 y0 = *(const float4*)(Bbase + k0);
            float4 y1 = *(const float4*)(Bbase + k0 + 4);
            na  = fmaf(x0.x, x0.x, fmaf(x0.y, x0.y, fmaf(x0.z, x0.z, fmaf(x0.w, x0.w, na))));
            na  = fmaf(x1.x, x1.x, fmaf(x1.y, x1.y, fmaf(x1.z, x1.z, fmaf(x1.w, x1.w, na))));
            nbm = fmaf(y0.x, y0.x, fmaf(y0.y, y0.y, fmaf(y0.z, y0.z, fmaf(y0.w, y0.w, nbm))));
            nbm = fmaf(y1.x, y1.x, fmaf(y1.y, y1.y, fmaf(y1.z, y1.z, fmaf(y1.w, y1.w, nbm))));
            float ax[8] = {x0.x, x0.y, x0.z, x0.w, x1.x, x1.y, x1.z, x1.w};
            float bx[8] = {y0.x, y0.y, y0.z, y0.w, y1.x, y1.y, y1.z, y1.w};
            #pragma unroll
            for (int e = 0; e < 8; e++) {
                unsigned ah = f2tf(ax[e]);
                unsigned al = f2tf(ax[e] - __uint_as_float(ah));
                unsigned bh = f2tf(bx[e]);
                unsigned bl = f2tf(bx[e] - __uint_as_float(bh));
                Apk[srow][soff + e] = make_uint2(ah, al);
                Bpk[srow][soff + e] = make_uint2(bh, bl);
            }
        }
        __syncthreads();

        // ---- MMA over 8 k-steps of this chunk ----
        #pragma unroll
        for (int ks = 0; ks < 8; ks++) {
            const int kk = ks * 8;
            uint2 fa0 = Apk[ar0][kk + t4];
            uint2 fa1 = Apk[ar1][kk + t4];
            uint2 fa2 = Apk[ar0][kk + t4 + 4];
            uint2 fa3 = Apk[ar1][kk + t4 + 4];
            uint2 fb0 = Bpk[brn][kk + t4];
            uint2 fb1 = Bpk[brn][kk + t4 + 4];
            // hi*hi, hi*lo, lo*hi (fixed order -> deterministic)
            mma_tf32(acc, fa0.x, fa1.x, fa2.x, fa3.x, fb0.x, fb1.x);
            mma_tf32(acc, fa0.x, fa1.x, fa2.x, fa3.x, fb0.y, fb1.y);
            mma_tf32(acc, fa0.y, fa1.y, fa2.y, fa3.y, fb0.x, fb1.x);
        }
    }

    // ---- norm reduce within 8-lane groups ----
    na  += __shfl_xor_sync(0xffffffffu, na, 1);
    na  += __shfl_xor_sync(0xffffffffu, na, 2);
    na  += __shfl_xor_sync(0xffffffffu, na, 4);
    nbm += __shfl_xor_sync(0xffffffffu, nbm, 1);
    nbm += __shfl_xor_sync(0xffffffffu, nbm, 2);
    nbm += __shfl_xor_sync(0xffffffffu, nbm, 4);
    if ((tid & 7) == 0) { sqA[srow] = na; sqB[srow] = nbm; }
    __syncthreads();

    // ---- epilogue: pd = max(sq_i + sq_j - 2 dot, 0), diag 0, mirror ----
    {
        const int gj0 = j0 + nb * 8 + 2 * t4;
        const float sb0 = sqB[nb * 8 + 2 * t4];
        const float sb1 = sqB[nb * 8 + 2 * t4 + 1];

        const int gi0 = i0 + mb * 16 + g;
        const float sa0 = sqA[mb * 16 + g];
        float v00 = fmaxf(sa0 + sb0 - 2.f * acc[0], 0.f);
        float v01 = fmaxf(sa0 + sb1 - 2.f * acc[1], 0.f);
        if (gi0 == gj0)     v00 = 0.f;
        if (gi0 == gj0 + 1) v01 = 0.f;
        *(float2*)(g_pd + gi0 * BN + gj0) = make_float2(v00, v01);

        const int gi1 = gi0 + 8;
        const float sa1 = sqA[mb * 16 + g + 8];
        float v10 = fmaxf(sa1 + sb0 - 2.f * acc[2], 0.f);
        float v11 = fmaxf(sa1 + sb1 - 2.f * acc[3], 0.f);
        if (gi1 == gj0)     v10 = 0.f;
        if (gi1 == gj0 + 1) v11 = 0.f;
        *(float2*)(g_pd + gi1 * BN + gj0) = make_float2(v10, v11);

        if (ti != tj) {
            g_pd[gj0 * BN + gi0]       = v00;
            g_pd[(gj0 + 1) * BN + gi0] = v01;
            g_pd[gj0 * BN + gi1]       = v10;
            g_pd[(gj0 + 1) * BN + gi1] = v11;
        }
    }
}

// ---------------------------------------------------------------------------
// Kernel B: warp-per-anchor semi-hard mining + fused final reduction.
// 128 CTAs x 128 threads; warp w of CTA cb owns anchor j = cb*4 + w.
// ---------------------------------------------------------------------------
__global__ void __launch_bounds__(128) mine_final(const int* __restrict__ labels,
                                                  float* __restrict__ out) {
    const int tid = threadIdx.x;
    const int lane = tid & 31, w = tid >> 5;
    const unsigned FULL = 0xffffffffu;

    __shared__ int   s_lab[BN];
    __shared__ float s_row[4][BN];
    __shared__ int s_last;

    #pragma unroll
    for (int k = tid; k < BN; k += 128) s_lab[k] = labels[k];
    __syncthreads();

    const int j = blockIdx.x * 4 + w;          // anchor (0..511)
    const int lj = s_lab[j];
    const float* rowp = g_pd + j * BN;

    float v[16];
    unsigned nmask = 0, pmask = 0;
    #pragma unroll
    for (int c = 0; c < 16; c++) {
        const int k = c * 32 + lane;
        v[c] = rowp[k];
        s_row[w][k] = v[c];
        const bool same = (s_lab[k] == lj);
        if (!same) nmask |= (1u << c);
        if (same && k != j) pmask |= (1u << c);
    }

    float mx = -FLT_MAX, mn = FLT_MAX;
    #pragma unroll
    for (int c = 0; c < 16; c++) {
        if ((nmask >> c) & 1) mx = fmaxf(mx, v[c]);
        mn = fminf(mn, v[c]);
    }
    #pragma unroll
    for (int o = 16; o; o >>= 1) {
        mx = fmaxf(mx, __shfl_xor_sync(FULL, mx, o));
        mn = fminf(mn, __shfl_xor_sync(FULL, mn, o));
    }
    const float ninside = (mx > -FLT_MAX) ? mx : mn;

    float wsum = 0.f;
    int cnt = 0;
    int pend = -1;
    #pragma unroll 1
    for (int c = 0; c < 16; c++) {
        unsigned pm = __ballot_sync(FULL, (pmask >> c) & 1);
        while (pm) {
            const int bb = __ffs(pm) - 1;
            pm &= pm - 1;
            const int i = c * 32 + bb;
            cnt++;
            if (pend < 0) { pend = i; continue; }
            const float t1 = s_row[w][pend];
            const float t2 = s_row[w][i];
            float m1 = FLT_MAX, m2 = FLT_MAX;
            #pragma unroll
            for (int cc = 0; cc < 16; cc++) {
                if ((nmask >> cc) & 1) {
                    const float x = v[cc];
                    if (x > t1) m1 = fminf(m1, x);
                    if (x > t2) m2 = fminf(m2, x);
                }
            }
            #pragma unroll
            for (int o = 16; o; o >>= 1) {
                m1 = fminf(m1, __shfl_xor_sync(FULL, m1, o));
                m2 = fminf(m2, __shfl_xor_sync(FULL, m2, o));
            }
            const float semi1 = (m1 < FLT_MAX) ? m1 : ninside;
            const float semi2 = (m2 < FLT_MAX) ? m2 : ninside;
            wsum += fmaxf(1.0f + t1 - semi1, 0.f);
            wsum += fmaxf(1.0f + t2 - semi2, 0.f);
            pend = -1;
        }
    }
    if (pend >= 0) {
        const float t1 = s_row[w][pend];
        float m1 = FLT_MAX;
        #pragma unroll
        for (int cc = 0; cc < 16; cc++) {
            if ((nmask >> cc) & 1) {
                const float x = v[cc];
                if (x > t1) m1 = fminf(m1, x);
            }
        }
        #pragma unroll
        for (int o = 16; o; o >>= 1)
            m1 = fminf(m1, __shfl_xor_sync(FULL, m1, o));
        const float semi1 = (m1 < FLT_MAX) ? m1 : ninside;
        wsum += fmaxf(1.0f + t1 - semi1, 0.f);
    }

    if (lane == 0) {
        g_ploss[j] = wsum;
        g_pcnt[j]  = cnt;
    }
    __syncthreads();
    if (tid == 0) {
        __threadfence();
        const unsigned int vd = atomicAdd(&g_done, 1u);
        s_last = (vd == (unsigned)(gridDim.x - 1)) ? 1 : 0;
    }
    __syncthreads();

    if (s_last) {
        __threadfence();  // acquire
        float s = 0.f, c = 0.f;
        #pragma unroll
        for (int r = 0; r < 4; r++) {
            s += g_ploss[tid + r * 128];
            c += (float)g_pcnt[tid + r * 128];
        }
        #pragma unroll
        for (int o = 16; o; o >>= 1) {
            s += __shfl_xor_sync(FULL, s, o);
            c += __shfl_xor_sync(FULL, c, o);
        }
        __shared__ float ss[4], cc2[4];
        if (lane == 0) { ss[w] = s; cc2[w] = c; }
        __syncthreads();
        if (tid == 0) {
            float ts = 0.f, tc = 0.f;
            #pragma unroll
            for (int i = 0; i < 4; i++) { ts += ss[i]; tc += cc2[i]; }
            out[0] = ts / tc;
            g_done = 0;   // reset for next graph replay
        }
    }
}

// ---------------------------------------------------------------------------
extern "C" void kernel_launch(void* const* d_in, const int* in_sizes, int n_in,
                              void* d_out, int out_size) {
    const float* emb = (const float*)d_in[0];
    const int* labels = (const int*)d_in[1];
    float* out = (float*)d_out;

    pd_mma<<<NBLK, 256>>>(emb);
    mine_final<<<MBLK, 128>>>(labels, out);
}

// round 11
// speedup vs baseline: 1.1254x; 1.1254x over previous
#include <cuda_runtime.h>
#include <float.h>

#define BN 512
#define DN 256
#define NT 16            // 512 / 32 tiles per dim
#define NBLK 136         // NT*(NT+1)/2 upper-triangular tiles
#define MBLK 128         // mine kernel CTAs (4 warps = 4 anchors each)

// Scratch (no allocations allowed)
__device__ float g_pd[BN * BN];
__device__ float g_ploss[BN];
__device__ int   g_pcnt[BN];
__device__ unsigned int g_done;    // reset by last CTA each call

// ---------------------------------------------------------------------------
// Kernel A: symmetric pairwise sq-distance GEMM, norms fused into tile loads,
// global-load prefetch for chunk 2. 136 CTAs x 256 threads, split-K x4.
// ---------------------------------------------------------------------------
__global__ void __launch_bounds__(256) pd_fused(const float* __restrict__ emb) {
    __shared__ float As[4][32][32];   // reused as partial-sum scratch after loop
    __shared__ float Bs[4][32][32];
    __shared__ float nA[4][32], nB[4][32];
    __shared__ float sqA[32], sqB[32];

    const int tid = threadIdx.x;

    // decode linear block -> (ti, tj), ti <= tj
    int b = blockIdx.x, ti = 0;
    while (b >= NT - ti) { b -= NT - ti; ti++; }
    const int tj = ti + b;
    const int i0 = ti * 32, j0 = tj * 32;

    const int t    = tid & 63;
    const int g    = tid >> 6;             // 0..3, k in [g*64, g*64+64)
    const int lr   = t >> 1;               // load row 0..31
    const int half = t & 1;                // k-half within 32-chunk
    const int ty   = t >> 3;               // 0..7 -> 4 i-rows
    const int tx   = t & 7;                // 0..7 -> 4 j-cols

    float acc[4][4] = {};
    float na = 0.f, nb = 0.f;              // norm partials

    {
        const float* Arow = emb + (i0 + lr) * DN + g * 64;
        const float* Brow = emb + (j0 + lr) * DN + g * 64;

        // prefetch chunk 0 into registers
        float4 pa[4], pb[4];
        #pragma unroll
        for (int e = 0; e < 4; e++) {
            const int ko = half * 16 + e * 4;
            pa[e] = *(const float4*)(Arow + ko);
            pb[e] = *(const float4*)(Brow + ko);
        }

        #pragma unroll
        for (int c0 = 0; c0 < 64; c0 += 32) {
            __syncthreads();
            #pragma unroll
            for (int e = 0; e < 4; e++) {
                const int ko = half * 16 + e * 4;
                const float4 a4 = pa[e];
                const float4 b4 = pb[e];
                na = fmaf(a4.x, a4.x, fmaf(a4.y, a4.y, fmaf(a4.z, a4.z, fmaf(a4.w, a4.w, na))));
                nb = fmaf(b4.x, b4.x, fmaf(b4.y, b4.y, fmaf(b4.z, b4.z, fmaf(b4.w, b4.w, nb))));
                As[g][ko + 0][lr] = a4.x; As[g][ko + 1][lr] = a4.y;
                As[g][ko + 2][lr] = a4.z; As[g][ko + 3][lr] = a4.w;
                Bs[g][ko + 0][lr] = b4.x; Bs[g][ko + 1][lr] = b4.y;
                Bs[g][ko + 2][lr] = b4.z; Bs[g][ko + 3][lr] = b4.w;
            }
            __syncthreads();
            // prefetch next chunk (issues before FMA block, hidden under it)
            if (c0 == 0) {
                #pragma unroll
                for (int e = 0; e < 4; e++) {
                    const int ko = half * 16 + e * 4;
                    pa[e] = *(const float4*)(Arow + 32 + ko);
                    pb[e] = *(const float4*)(Brow + 32 + ko);
                }
            }
            #pragma unroll
            for (int kk = 0; kk < 32; kk++) {
                float4 av = *(const float4*)&As[g][kk][ty << 2];
                float4 bv = *(const float4*)&Bs[g][kk][tx << 2];
                float ar[4] = {av.x, av.y, av.z, av.w};
                float br[4] = {bv.x, bv.y, bv.z, bv.w};
                #pragma unroll
                for (int u = 0; u < 4; u++)
                    #pragma unroll
                    for (int v = 0; v < 4; v++)
                        acc[u][v] = fmaf(ar[u], br[v], acc[u][v]);
            }
        }
    }

    // ---- norm combine: lanes (2m, 2m+1) share row lr ----
    na += __shfl_xor_sync(0xffffffffu, na, 1);
    nb += __shfl_xor_sync(0xffffffffu, nb, 1);
    if (!half) { nA[g][lr] = na; nB[g][lr] = nb; }
    __syncthreads();
    if (g == 0) {
        if (t < 32) sqA[t] = (nA[0][t] + nA[1][t]) + (nA[2][t] + nA[3][t]);
        else        sqB[t - 32] = (nB[0][t - 32] + nB[1][t - 32]) + (nB[2][t - 32] + nB[3][t - 32]);
    }
    // groups 1..3 park their partials in As-scratch (disjoint from sqA/sqB)
    if (g > 0) {
        float* dst = &As[0][0][0] + ((g - 1) * 64 + t) * 16;
        #pragma unroll
        for (int u = 0; u < 4; u++)
            #pragma unroll
            for (int v = 0; v < 4; v++) dst[u * 4 + v] = acc[u][v];
    }
    __syncthreads();

    if (g == 0) {
        const float* p1 = &As[0][0][0] + (0 * 64 + t) * 16;
        const float* p2 = &As[0][0][0] + (1 * 64 + t) * 16;
        const float* p3 = &As[0][0][0] + (2 * 64 + t) * 16;
        float d[4][4];
        #pragma unroll
        for (int u = 0; u < 4; u++) {
            const int gi = i0 + (ty << 2) + u;
            const float sqi = sqA[(ty << 2) + u];
            #pragma unroll
            for (int v = 0; v < 4; v++) {
                const int gj = j0 + (tx << 2) + v;
                const int e = u * 4 + v;
                const float dot = (acc[u][v] + p1[e]) + (p2[e] + p3[e]);
                float val = fmaxf(sqi + sqB[(tx << 2) + v] - 2.f * dot, 0.f);
                if (gi == gj) val = 0.f;
                d[u][v] = val;
            }
            *(float4*)(g_pd + gi * BN + j0 + (tx << 2)) =
                make_float4(d[u][0], d[u][1], d[u][2], d[u][3]);
        }
        if (ti != tj) {
            #pragma unroll
            for (int v = 0; v < 4; v++) {
                const int gj = j0 + (tx << 2) + v;
                *(float2*)(g_pd + gj * BN + i0 + (ty << 2)) =
                    make_float2(d[0][v], d[1][v]);
                *(float2*)(g_pd + gj * BN + i0 + (ty << 2) + 2) =
                    make_float2(d[2][v], d[3][v]);
            }
        }
    }
}

// ---------------------------------------------------------------------------
// Kernel B: warp-per-anchor semi-hard mining + fused final reduction.
// 128 CTAs x 128 threads; warp w of CTA cb owns anchor j = cb*4 + w.
// Row register layout: v[c*4+e] = row[c*128 + lane*4 + e] (LDG.128 loads).
// ---------------------------------------------------------------------------
__global__ void __launch_bounds__(128) mine_final(const int* __restrict__ labels,
                                                  float* __restrict__ out) {
    const int tid = threadIdx.x;
    const int lane = tid & 31, w = tid >> 5;
    const unsigned FULL = 0xffffffffu;

    __shared__ int   s_lab[BN];
    __shared__ float s_row[4][BN];
    __shared__ int s_last;

    #pragma unroll
    for (int k = tid; k < BN; k += 128) s_lab[k] = labels[k];
    __syncthreads();

    const int j = blockIdx.x * 4 + w;          // anchor (0..511)
    const int lj = s_lab[j];
    const float* rowp = g_pd + j * BN;

    // load row as 4x LDG.128; build negativity/positivity masks
    float v[16];
    unsigned nmask = 0, pmask = 0;
    #pragma unroll
    for (int c = 0; c < 4; c++) {
        const int kb = c * 128 + lane * 4;
        const float4 r4 = *(const float4*)(rowp + kb);
        v[c * 4 + 0] = r4.x; v[c * 4 + 1] = r4.y;
        v[c * 4 + 2] = r4.z; v[c * 4 + 3] = r4.w;
        *(float4*)&s_row[w][kb] = r4;
        #pragma unroll
        for (int e = 0; e < 4; e++) {
            const int k = kb + e;
            const bool same = (s_lab[k] == lj);
            if (!same) nmask |= (1u << (c * 4 + e));
            if (same && k != j) pmask |= (1u << (c * 4 + e));
        }
    }

    // neg_inside: max over negatives (fallback: min over full row)
    float mx = -FLT_MAX, mn = FLT_MAX;
    #pragma unroll
    for (int c = 0; c < 16; c++) {
        if ((nmask >> c) & 1) mx = fmaxf(mx, v[c]);
        mn = fminf(mn, v[c]);
    }
    #pragma unroll
    for (int o = 16; o; o >>= 1) {
        mx = fmaxf(mx, __shfl_xor_sync(FULL, mx, o));
        mn = fminf(mn, __shfl_xor_sync(FULL, mn, o));
    }
    const float ninside = (mx > -FLT_MAX) ? mx : mn;

    // iterate positives deterministically, process in pairs (overlap shfl chains)
    float wsum = 0.f;
    int cnt = 0;
    int pend = -1;
    #pragma unroll 1
    for (int ce = 0; ce < 16; ce++) {
        unsigned pm = __ballot_sync(FULL, (pmask >> ce) & 1);
        while (pm) {
            const int bb = __ffs(pm) - 1;
            pm &= pm - 1;
            const int i = (ce >> 2) * 128 + bb * 4 + (ce & 3);
            cnt++;
            if (pend < 0) { pend = i; continue; }
            const float t1 = s_row[w][pend];
            const float t2 = s_row[w][i];
            float m1 = FLT_MAX, m2 = FLT_MAX;
            #pragma unroll
            for (int cc = 0; cc < 16; cc++) {
                if ((nmask >> cc) & 1) {
                    const float x = v[cc];
                    if (x > t1) m1 = fminf(m1, x);
                    if (x > t2) m2 = fminf(m2, x);
                }
            }
            #pragma unroll
            for (int o = 16; o; o >>= 1) {
                m1 = fminf(m1, __shfl_xor_sync(FULL, m1, o));
                m2 = fminf(m2, __shfl_xor_sync(FULL, m2, o));
            }
            const float semi1 = (m1 < FLT_MAX) ? m1 : ninside;
            const float semi2 = (m2 < FLT_MAX) ? m2 : ninside;
            wsum += fmaxf(1.0f + t1 - semi1, 0.f);
            wsum += fmaxf(1.0f + t2 - semi2, 0.f);
            pend = -1;
        }
    }
    if (pend >= 0) {
        const float t1 = s_row[w][pend];
        float m1 = FLT_MAX;
        #pragma unroll
        for (int cc = 0; cc < 16; cc++) {
            if ((nmask >> cc) & 1) {
                const float x = v[cc];
                if (x > t1) m1 = fminf(m1, x);
            }
        }
        #pragma unroll
        for (int o = 16; o; o >>= 1)
            m1 = fminf(m1, __shfl_xor_sync(FULL, m1, o));
        const float semi1 = (m1 < FLT_MAX) ? m1 : ninside;
        wsum += fmaxf(1.0f + t1 - semi1, 0.f);
    }

    if (lane == 0) {
        g_ploss[j] = wsum;
        g_pcnt[j]  = cnt;
    }
    __syncthreads();
    if (tid == 0) {
        __threadfence();
        const unsigned int vd = atomicAdd(&g_done, 1u);
        s_last = (vd == (unsigned)(gridDim.x - 1)) ? 1 : 0;
    }
    __syncthreads();

    // last CTA: deterministic final reduction over fixed-order arrays
    if (s_last) {
        __threadfence();  // acquire
        float s = 0.f, c = 0.f;
        #pragma unroll
        for (int r = 0; r < 4; r++) {
            s += g_ploss[tid + r * 128];
            c += (float)g_pcnt[tid + r * 128];
        }
        #pragma unroll
        for (int o = 16; o; o >>= 1) {
            s += __shfl_xor_sync(FULL, s, o);
            c += __shfl_xor_sync(FULL, c, o);
        }
        __shared__ float ss[4], cc2[4];
        if (lane == 0) { ss[w] = s; cc2[w] = c; }
        __syncthreads();
        if (tid == 0) {
            float ts = 0.f, tc = 0.f;
            #pragma unroll
            for (int i = 0; i < 4; i++) { ts += ss[i]; tc += cc2[i]; }
            out[0] = ts / tc;
            g_done = 0;   // reset for next graph replay
        }
    }
}

// ---------------------------------------------------------------------------
extern "C" void kernel_launch(void* const* d_in, const int* in_sizes, int n_in,
                              void* d_out, int out_size) {
    const float* emb = (const float*)d_in[0];
    const int* labels = (const int*)d_in[1];
    float* out = (float*)d_out;

    pd_fused<<<NBLK, 256>>>(emb);
    mine_final<<<MBLK, 128>>>(labels, out);
}